// round 12
// baseline (speedup 1.0000x reference)
#include <cuda_runtime.h>
#include <cstdint>
#include <cstddef>

#define TT 4096
#define NT 256
#define NA 64

// Scratch (no allocations allowed -> __device__ globals)
__device__ float g_tmg[TT * NT];    // gathered rows: tm[lx[t]][n], t-major (4MB)
__device__ float g_gbuf[NA * TT];   // driver output g[a][t] (1MB)
__device__ float g_abuf[TT];        // a_t = kc_t * tm[lx[t-1]][lx[t]]
__device__ float g_kcbuf[TT];       // kc_t = log2e / diff[lx[t]]

__device__ __forceinline__ float fex2(float x) {
    float y; asm("ex2.approx.f32 %0, %1;" : "=f"(y) : "f"(x)); return y;
}
__device__ __forceinline__ float frcp(float x) {
    float y; asm("rcp.approx.f32 %0, %1;" : "=f"(y) : "f"(x)); return y;
}

// ---------------------------------------------------------------------------
// Prep: gather tm rows in t-order + per-step driver constants
// ---------------------------------------------------------------------------
__global__ void prep_kernel(const int* __restrict__ lx,
                            const float* __restrict__ tm,
                            const float* __restrict__ diff) {
    int t = blockIdx.x;
    int n = threadIdx.x;
    int c = lx[t];
    g_tmg[t * NT + n] = tm[c * NT + n];
    if (n == 0) {
        float kc = 1.4426950408889634f * frcp(diff[c]);
        g_kcbuf[t] = kc;
        g_abuf[t] = (t == 0) ? 0.0f : tm[lx[t - 1] * NT + c] * kc;
    }
}

// ---------------------------------------------------------------------------
// Driver: one warp per algo. Computes g[a][t] for all t.
// State R(n) held as 8 regs/lane (n = lane*8 + j). Pipelined recurrence:
//   y_t = pre_t + a_t * g_{t-1},   pre_{t+1} = mem*kc_{t+1}*R_{t-1}(lx[t+1])
//   sp  = 1 - 2/(1+exp2(y)),  g_t = eff + boost*sp
//   R(n) <- mem*R(n) + tmg[t][n]*g_t
// ---------------------------------------------------------------------------
#define DRV_STEP(CURBUF, t_)                                                   \
    do {                                                                       \
        int t = (t_);                                                          \
        float y = fmaf(s_a[t], gprev, pre);                                    \
        float e = fex2(y);                                                     \
        float r1 = frcp(1.0f + e);                                             \
        float sp = fmaf(-2.0f, r1, 1.0f);                                      \
        float g = fmaf(boost, sp, eff);                                        \
        gout[t] = g;                                                           \
        int tc = (t < TT - 1) ? t + 1 : t;                                     \
        int c1 = (int)s_lxb[tc];                                               \
        float kc1 = s_kc[tc];                                                  \
        int sl = c1 & 7;                                                       \
        float x0 = (sl & 1) ? Sa.y : Sa.x;                                     \
        float x1 = (sl & 1) ? Sa.w : Sa.z;                                     \
        float x2 = (sl & 1) ? Sb.y : Sb.x;                                     \
        float x3 = (sl & 1) ? Sb.w : Sb.z;                                     \
        float y0 = (sl & 2) ? x1 : x0;                                         \
        float y1 = (sl & 2) ? x3 : x2;                                         \
        float rsel = (sl & 4) ? y1 : y0;                                       \
        float v2 = __shfl_sync(0xffffffffu, rsel, c1 >> 3);                    \
        pre = (mem * kc1) * v2;                                                \
        float4 u = CURBUF[2 * ((t_) & 7)];                                     \
        float4 w = CURBUF[2 * ((t_) & 7) + 1];                                 \
        Sa.x = fmaf(Sa.x, mem, u.x * g);                                       \
        Sa.y = fmaf(Sa.y, mem, u.y * g);                                       \
        Sa.z = fmaf(Sa.z, mem, u.z * g);                                       \
        Sa.w = fmaf(Sa.w, mem, u.w * g);                                       \
        Sb.x = fmaf(Sb.x, mem, w.x * g);                                       \
        Sb.y = fmaf(Sb.y, mem, w.y * g);                                       \
        Sb.z = fmaf(Sb.z, mem, w.z * g);                                       \
        Sb.w = fmaf(Sb.w, mem, w.w * g);                                       \
        gprev = g;                                                             \
    } while (0)

#define DRV_TILE(CURBUF, NXTBUF, base_, nbase_)                                \
    do {                                                                       \
        _Pragma("unroll") for (int r = 0; r < 8; r++) {                        \
            NXTBUF[2 * r] = trow[((nbase_) + r) * 64];                         \
            NXTBUF[2 * r + 1] = trow[((nbase_) + r) * 64 + 1];                 \
        }                                                                      \
        _Pragma("unroll") for (int j = 0; j < 8; j++) {                        \
            DRV_STEP(CURBUF, (base_) + j);                                     \
        }                                                                      \
    } while (0)

__global__ void __launch_bounds__(32, 1)
driver_kernel(const int* __restrict__ lx,
              const float* __restrict__ effp,
              const float* __restrict__ memp,
              const float* __restrict__ boostp) {
    __shared__ float s_a[TT];
    __shared__ float s_kc[TT];
    __shared__ unsigned char s_lxb[TT];

    int a = blockIdx.x;
    int lane = threadIdx.x;

    // Stage scalar streams into shared memory
    for (int i = lane; i < TT / 4; i += 32) {
        ((float4*)s_a)[i] = ((const float4*)g_abuf)[i];
        ((float4*)s_kc)[i] = ((const float4*)g_kcbuf)[i];
        int4 q = ((const int4*)lx)[i];
        uchar4 p;
        p.x = (unsigned char)q.x; p.y = (unsigned char)q.y;
        p.z = (unsigned char)q.z; p.w = (unsigned char)q.w;
        ((uchar4*)s_lxb)[i] = p;
    }
    __syncwarp();

    float eff = effp[a];
    float mem = memp[a];
    float boost = boostp[a];

    float4 Sa = make_float4(0.f, 0.f, 0.f, 0.f);
    float4 Sb = make_float4(0.f, 0.f, 0.f, 0.f);
    float gprev = 0.0f, pre = 0.0f;
    float* gout = g_gbuf + a * TT;

    // lane owns n = lane*8 + j ; row t lives at float4 index t*64 + lane*2
    const float4* trow = ((const float4*)g_tmg) + lane * 2;

    float4 cu[16], nx[16];
#pragma unroll
    for (int r = 0; r < 8; r++) {
        cu[2 * r] = trow[r * 64];
        cu[2 * r + 1] = trow[r * 64 + 1];
    }

    for (int tp = 0; tp < 256; ++tp) {
        int b0 = tp * 16;
        DRV_TILE(cu, nx, b0, b0 + 8);
        int b1 = b0 + 8;
        int nb = (tp < 255) ? b1 + 8 : b1;   // clamp last prefetch
        DRV_TILE(nx, cu, b1, nb);
    }
}

// ---------------------------------------------------------------------------
// Output: one thread per (a,n). Sequential linear scan over t with precomputed
// g[a][t]; write tanh to out[a][n][t+1]. out[a][n][0] = 0.
// ---------------------------------------------------------------------------
__global__ void __launch_bounds__(128)
out_kernel(const float* __restrict__ diff,
           const float* __restrict__ memp,
           float* __restrict__ out) {
    int gtid = blockIdx.x * 128 + threadIdx.x;   // 0..16383
    int a = gtid >> 8;
    int n = gtid & 255;

    float mem = memp[a];
    float kn = 1.4426950408889634f * frcp(diff[n]);

    const float4* gp = (const float4*)(g_gbuf + a * TT);
    const float* tp = g_tmg + n;
    float* op = out + (size_t)gtid * (size_t)(TT + 1);
    op[0] = 0.0f;

    float res = 0.0f;

    float4 gA = gp[0], gB = gp[1];
    float tv[8];
#pragma unroll
    for (int j = 0; j < 8; j++) tv[j] = tp[j * NT];

    for (int t = 0; t < TT; t += 8) {
        // prefetch next batch (clamped on last)
        int tn = (t + 8 < TT) ? t + 8 : t;
        float4 gA2 = gp[tn / 4];
        float4 gB2 = gp[tn / 4 + 1];
        float tv2[8];
#pragma unroll
        for (int j = 0; j < 8; j++) tv2[j] = tp[(tn + j) * NT];

        float gr[8] = {gA.x, gA.y, gA.z, gA.w, gB.x, gB.y, gB.z, gB.w};
#pragma unroll
        for (int j = 0; j < 8; j++) {
            res = fmaf(res, mem, tv[j] * gr[j]);
            float y = res * kn;
            float e = fex2(y);
            float r1 = frcp(1.0f + e);
            op[t + 1 + j] = fmaf(-2.0f, r1, 1.0f);
        }
        gA = gA2; gB = gB2;
#pragma unroll
        for (int j = 0; j < 8; j++) tv[j] = tv2[j];
    }
}

// ---------------------------------------------------------------------------
// Launch
// ---------------------------------------------------------------------------
extern "C" void kernel_launch(void* const* d_in, const int* in_sizes, int n_in,
                              void* d_out, int out_size) {
    const int* lx = (const int*)d_in[0];            // (4096,) int32
    const float* tm = (const float*)d_in[1];        // (256,256)
    const float* diff = (const float*)d_in[2];      // (256,)
    const float* eff = (const float*)d_in[3];       // (64,)
    const float* mem = (const float*)d_in[4];       // (64,)
    const float* boost = (const float*)d_in[5];     // (64,)
    float* out = (float*)d_out;                     // (64,256,4097)

    prep_kernel<<<TT, NT>>>(lx, tm, diff);
    driver_kernel<<<NA, 32>>>(lx, eff, mem, boost);
    out_kernel<<<128, 128>>>(diff, mem, out);
}

// round 15
// speedup vs baseline: 1.5829x; 1.5829x over previous
#include <cuda_runtime.h>
#include <cstdint>
#include <cstddef>

#define TT 4096
#define NT 256
#define NA 64
#define TSTRIDE 4128   // padded row stride (floats)
#define GSTRIDE 4128

// Scratch (no allocations allowed -> __device__ globals)
__device__ float g_tmg[TT * NT];              // tm[lx[t]][n], t-major (driver)
__device__ float g_tmT[NT * TSTRIDE];         // shifted transpose: [n][p]=tm[lx[p-1]][n], [n][0]=0
__device__ float g_gbuf[NA * GSTRIDE];        // shifted driver output: gS[a][p]=g_{p-1}, [a][0]=0
__device__ float g_abuf[TT];                  // a_t = kc_t * tm[lx[t-1]][lx[t]]
__device__ float g_kcbuf[TT];                 // kc_t = log2e / diff[lx[t]]

__device__ __forceinline__ float fex2(float x) {
    float y; asm("ex2.approx.f32 %0, %1;" : "=f"(y) : "f"(x)); return y;
}
__device__ __forceinline__ float frcp(float x) {
    float y; asm("rcp.approx.f32 %0, %1;" : "=f"(y) : "f"(x)); return y;
}

// ---------------------------------------------------------------------------
// Prep: gather tm rows (both layouts) + per-step driver constants
// ---------------------------------------------------------------------------
__global__ void prep_kernel(const int* __restrict__ lx,
                            const float* __restrict__ tm,
                            const float* __restrict__ diff) {
    int t = blockIdx.x;
    int n = threadIdx.x;
    int c = lx[t];
    float v = tm[c * NT + n];
    g_tmg[t * NT + n] = v;
    g_tmT[n * TSTRIDE + (t + 1)] = v;          // shifted by +1
    if (t == 0) {
        g_tmT[n * TSTRIDE] = 0.0f;             // p=0 slot
        if (n < NA) g_gbuf[n * GSTRIDE] = 0.0f;
    }
    if (n == 0) {
        float kc = 1.4426950408889634f * frcp(diff[c]);
        g_kcbuf[t] = kc;
        g_abuf[t] = (t == 0) ? 0.0f : tm[lx[t - 1] * NT + c] * kc;
    }
}

// ---------------------------------------------------------------------------
// Driver: one warp per algo. Recurrence on r1 = 1/(1+2^y):
//   y_t  = pp_t - a2_t * r1_{t-1};  r1_t = rcp(1 + ex2(y_t))
//   g_t  = c1 - c2*r1_t            (c1 = eff+boost, c2 = 2*boost)
//   R(n) <- mem*R(n) + tmg[t][n]*g_t
// pp_{t+1} = mem*kc_{t+1}*R_{t-1}(c_{t+1}) + a_{t+1}*c1  (off-chain lookahead)
// g stored shifted: gS[a][t+1] = g_t (lane-staged, 1 coalesced STG per 32 steps)
// ---------------------------------------------------------------------------
#define DRV_STEP(CURBUF, t_)                                                   \
    do {                                                                       \
        int t = (t_);                                                          \
        float y = fmaf(-a2c, r1p, ppc);                                        \
        float e = fex2(y);                                                     \
        float r1n = frcp(1.0f + e);                                            \
        float g = fmaf(-c2, r1n, c1);                                          \
        int tc = (t < TT - 1) ? t + 1 : t;                                     \
        int cx = (int)s_lxb[tc];                                               \
        float kc1 = s_kc[tc];                                                  \
        int sl = cx & 7;                                                       \
        float x0 = (sl & 1) ? Sa.y : Sa.x;                                     \
        float x1 = (sl & 1) ? Sa.w : Sa.z;                                     \
        float x2 = (sl & 1) ? Sb.y : Sb.x;                                     \
        float x3 = (sl & 1) ? Sb.w : Sb.z;                                     \
        float y0 = (sl & 2) ? x1 : x0;                                         \
        float y1 = (sl & 2) ? x3 : x2;                                         \
        float rsel = (sl & 4) ? y1 : y0;                                       \
        float v2 = __shfl_sync(0xffffffffu, rsel, cx >> 3);                    \
        float pre = (mem * kc1) * v2;                                          \
        float an = s_a[tc];                                                    \
        float ppn = fmaf(an, c1, pre);                                         \
        float a2n = an * c2;                                                   \
        float4 u = CURBUF[2 * ((t_) & 7)];                                     \
        float4 w = CURBUF[2 * ((t_) & 7) + 1];                                 \
        Sa.x = fmaf(Sa.x, mem, u.x * g);                                       \
        Sa.y = fmaf(Sa.y, mem, u.y * g);                                       \
        Sa.z = fmaf(Sa.z, mem, u.z * g);                                       \
        Sa.w = fmaf(Sa.w, mem, u.w * g);                                       \
        Sb.x = fmaf(Sb.x, mem, w.x * g);                                       \
        Sb.y = fmaf(Sb.y, mem, w.y * g);                                       \
        Sb.z = fmaf(Sb.z, mem, w.z * g);                                       \
        Sb.w = fmaf(Sb.w, mem, w.w * g);                                       \
        greg = (lane == (t & 31)) ? g : greg;                                  \
        r1p = r1n; ppc = ppn; a2c = a2n;                                       \
    } while (0)

#define DRV_TILE(CURBUF, NXTBUF, base_, nbase_)                                \
    do {                                                                       \
        _Pragma("unroll") for (int r = 0; r < 8; r++) {                        \
            NXTBUF[2 * r] = trow[((nbase_) + r) * 64];                         \
            NXTBUF[2 * r + 1] = trow[((nbase_) + r) * 64 + 1];                 \
        }                                                                      \
        _Pragma("unroll") for (int j = 0; j < 8; j++) {                        \
            DRV_STEP(CURBUF, (base_) + j);                                     \
        }                                                                      \
    } while (0)

__global__ void __launch_bounds__(32, 1)
driver_kernel(const int* __restrict__ lx,
              const float* __restrict__ effp,
              const float* __restrict__ memp,
              const float* __restrict__ boostp) {
    __shared__ float s_a[TT];
    __shared__ float s_kc[TT];
    __shared__ unsigned char s_lxb[TT];

    int a = blockIdx.x;
    int lane = threadIdx.x;

    for (int i = lane; i < TT / 4; i += 32) {
        ((float4*)s_a)[i] = ((const float4*)g_abuf)[i];
        ((float4*)s_kc)[i] = ((const float4*)g_kcbuf)[i];
        int4 q = ((const int4*)lx)[i];
        uchar4 p;
        p.x = (unsigned char)q.x; p.y = (unsigned char)q.y;
        p.z = (unsigned char)q.z; p.w = (unsigned char)q.w;
        ((uchar4*)s_lxb)[i] = p;
    }
    __syncwarp();

    float eff = effp[a];
    float mem = memp[a];
    float boost = boostp[a];
    float c1 = eff + boost;
    float c2 = 2.0f * boost;

    float4 Sa = make_float4(0.f, 0.f, 0.f, 0.f);
    float4 Sb = make_float4(0.f, 0.f, 0.f, 0.f);
    float r1p = 0.5f, ppc = 0.0f, a2c = 0.0f, greg = 0.0f;
    float* gout = g_gbuf + a * GSTRIDE;

    const float4* trow = ((const float4*)g_tmg) + lane * 2;

    float4 cu[16], nx[16];
#pragma unroll
    for (int r = 0; r < 8; r++) {
        cu[2 * r] = trow[r * 64];
        cu[2 * r + 1] = trow[r * 64 + 1];
    }

    for (int tp = 0; tp < 256; ++tp) {
        int b0 = tp * 16;
        DRV_TILE(cu, nx, b0, b0 + 8);
        int b1 = b0 + 8;
        int nb = (tp < 255) ? b1 + 8 : b1;
        DRV_TILE(nx, cu, b1, nb);
        if (tp & 1) {
            gout[(tp - 1) * 16 + 1 + lane] = greg;   // gS[p]=g_{p-1}, p in [(tp-1)*16+1, +32]
        }
    }
}

// ---------------------------------------------------------------------------
// Output: warp-per-(a,n) row. Interleaved warp scan: each iteration covers
// 128 consecutive positions as 4 sub-chunks of 32 (one element per lane), so
// ALL global loads/stores are scalar and fully coalesced — no 16B alignment
// requirement on the 4097-float output rows.
// Block = 8 warps covering 2 algos x 4 tasks (scratch rows L1-shared).
// ---------------------------------------------------------------------------
__global__ void __launch_bounds__(256)
out_kernel(const float* __restrict__ diff,
           const float* __restrict__ memp,
           float* __restrict__ out) {
    int wid = threadIdx.x >> 5;
    int lane = threadIdx.x & 31;
    int bn = blockIdx.x & 63;            // 64 n-quads
    int ba = blockIdx.x >> 6;            // 32 a-pairs
    int a = ba * 2 + (wid >> 2);
    int n = bn * 4 + (wid & 3);

    float m = memp[a];
    float kn = 1.4426950408889634f * frcp(diff[n]);

    float mp1 = m;
    float mp2 = mp1 * mp1;
    float mp4 = mp2 * mp2;
    float mp8 = mp4 * mp4;
    float mp16 = mp8 * mp8;
    float m32 = mp16 * mp16;
    // mlane = m^lane (binary ladder)
    float mlane = 1.0f, b = m;
    if (lane & 1) mlane *= b;
    b *= b;
    if (lane & 2) mlane *= b;
    b *= b;
    if (lane & 4) mlane *= b;
    b *= b;
    if (lane & 8) mlane *= b;
    b *= b;
    if (lane & 16) mlane *= b;
    float mlp1 = mlane * m;              // m^{lane+1}

    const float* tp = g_tmT + (size_t)n * TSTRIDE;
    const float* gp = g_gbuf + (size_t)a * GSTRIDE;
    float* op = out + ((size_t)a * NT + n) * (size_t)(TT + 1);

    float carry = 0.0f;                  // res at last position of previous chunk

#pragma unroll 1
    for (int it = 0; it < 32; ++it) {
        int base = it * 128 + lane;
#pragma unroll
        for (int s = 0; s < 4; ++s) {
            int q = base + s * 32;
            float c = tp[q] * gp[q];
            float x = c, v;
            v = __shfl_up_sync(0xffffffffu, x, 1);  if (lane >= 1)  x = fmaf(mp1, v, x);
            v = __shfl_up_sync(0xffffffffu, x, 2);  if (lane >= 2)  x = fmaf(mp2, v, x);
            v = __shfl_up_sync(0xffffffffu, x, 4);  if (lane >= 4)  x = fmaf(mp4, v, x);
            v = __shfl_up_sync(0xffffffffu, x, 8);  if (lane >= 8)  x = fmaf(mp8, v, x);
            v = __shfl_up_sync(0xffffffffu, x, 16); if (lane >= 16) x = fmaf(mp16, v, x);
            float res = fmaf(mlp1, carry, x);
            carry = __shfl_sync(0xffffffffu, res, 31);
            float e = fex2(res * kn);
            float r1 = frcp(1.0f + e);
            op[q] = fmaf(-2.0f, r1, 1.0f);
        }
    }

    // tail element p = 4096
    if (lane == 0) {
        float c = tp[TT] * gp[TT];
        float r = fmaf(m, carry, c);
        op[TT] = fmaf(-2.0f, frcp(1.0f + fex2(r * kn)), 1.0f);
    }
    (void)m32;
}

// ---------------------------------------------------------------------------
// Launch
// ---------------------------------------------------------------------------
extern "C" void kernel_launch(void* const* d_in, const int* in_sizes, int n_in,
                              void* d_out, int out_size) {
    const int* lx = (const int*)d_in[0];            // (4096,) int32
    const float* tm = (const float*)d_in[1];        // (256,256)
    const float* diff = (const float*)d_in[2];      // (256,)
    const float* eff = (const float*)d_in[3];       // (64,)
    const float* mem = (const float*)d_in[4];       // (64,)
    const float* boost = (const float*)d_in[5];     // (64,)
    float* out = (float*)d_out;                     // (64,256,4097)

    prep_kernel<<<TT, NT>>>(lx, tm, diff);
    driver_kernel<<<NA, 32>>>(lx, eff, mem, boost);
    out_kernel<<<2048, 256>>>(diff, mem, out);
}

// round 16
// speedup vs baseline: 1.6346x; 1.0327x over previous
#include <cuda_runtime.h>
#include <cstdint>
#include <cstddef>

#define TT 4096
#define NT 256
#define NA 64
#define TSTRIDE 4128   // padded row stride (floats)
#define GSTRIDE 4128

// Scratch (no allocations allowed -> __device__ globals)
__device__ float g_tmg[TT * NT];              // tm[lx[t]][n], t-major (driver)
__device__ float g_tmS[NT * TSTRIDE];         // shifted+prescaled: [n][p]=tm[lx[p-1]][n]/(2*diff[n]); [n][0]=0
__device__ float g_gbuf[NA * GSTRIDE];        // shifted driver output: gS[a][p]=g_{p-1}, [a][0]=0
__device__ float2 g_ak[TT];                   // {a_t, kc_t}

__device__ __forceinline__ float fex2(float x) {
    float y; asm("ex2.approx.f32 %0, %1;" : "=f"(y) : "f"(x)); return y;
}
__device__ __forceinline__ float frcp(float x) {
    float y; asm("rcp.approx.f32 %0, %1;" : "=f"(y) : "f"(x)); return y;
}
__device__ __forceinline__ float ftanh(float x) {
    float y; asm("tanh.approx.f32 %0, %1;" : "=f"(y) : "f"(x)); return y;
}

#define PACK2(d, lo, hi) asm("mov.b64 %0, {%1, %2};" : "=l"(d) : "f"(lo), "f"(hi))
#define UNPACK2(lo, hi, d) asm("mov.b64 {%0, %1}, %2;" : "=f"(lo), "=f"(hi) : "l"(d))
#define MUL2(d, a, b) asm("mul.rn.f32x2 %0, %1, %2;" : "=l"(d) : "l"(a), "l"(b))
#define FMA2(d, a, b, c) asm("fma.rn.f32x2 %0, %1, %2, %3;" : "=l"(d) : "l"(a), "l"(b), "l"(c))

// ---------------------------------------------------------------------------
// Prep: gather tm rows (both layouts) + per-step driver constants
// ---------------------------------------------------------------------------
__global__ void prep_kernel(const int* __restrict__ lx,
                            const float* __restrict__ tm,
                            const float* __restrict__ diff) {
    int t = blockIdx.x;
    int n = threadIdx.x;
    int c = lx[t];
    float v = tm[c * NT + n];
    g_tmg[t * NT + n] = v;
    float sc = 0.5f * frcp(diff[n]);           // 1/(2*diff[n])
    g_tmS[n * TSTRIDE + (t + 1)] = v * sc;     // shifted + prescaled
    if (t == 0) {
        g_tmS[n * TSTRIDE] = 0.0f;
        if (n < NA) g_gbuf[n * GSTRIDE] = 0.0f;
    }
    if (n == 0) {
        float kc = 1.4426950408889634f * frcp(diff[c]);
        float at = (t == 0) ? 0.0f : tm[lx[t - 1] * NT + c] * kc;
        g_ak[t] = make_float2(at, kc);
    }
}

// ---------------------------------------------------------------------------
// Driver: one warp per algo. Recurrence on r1 = 1/(1+2^y):
//   y_t  = pp_t - a2_t * r1_{t-1};  r1_t = rcp(1 + ex2(y_t))
//   g_t  = c1 - c2*r1_t            (c1 = eff+boost, c2 = 2*boost)
//   R(n) <- mem*R(n) + tmg[t][n]*g_t       (packed f32x2, lane owns cols
//                                           [4L..4L+3] and [128+4L..128+4L+3])
// pp_{t+1} = mem*kc_{t+1}*R_{t-1}(c_{t+1}) + a_{t+1}*c1  (off-chain lookahead)
// ---------------------------------------------------------------------------
#define DRV_STEP(CA, CB, NXA, NXB, NRP, t_, J)                                 \
    do {                                                                       \
        float y = fmaf(-a2c, r1p, ppc);                                        \
        float e = fex2(y);                                                     \
        float r1n = frcp(1.0f + e);                                            \
        float g = fmaf(-c2, r1n, c1);                                          \
        NXA[J] = *(const ulonglong2*)((NRP) + (J) * 1024);                     \
        NXB[J] = *(const ulonglong2*)((NRP) + (J) * 1024 + 512);               \
        int tc = (t_) + 1;                                                     \
        int cx = (int)s_lxb[tc];                                               \
        float2 ak = s_ak[tc];                                                  \
        unsigned long long Au = (cx & 128) ? Sb01 : Sa01;                      \
        unsigned long long Bu = (cx & 128) ? Sb23 : Sa23;                      \
        unsigned long long Cu = (cx & 2) ? Bu : Au;                            \
        float lo, hi;                                                          \
        UNPACK2(lo, hi, Cu);                                                   \
        float rsel = (cx & 1) ? hi : lo;                                       \
        float v2 = __shfl_sync(0xffffffffu, rsel, (cx >> 2) & 31);             \
        float pre = (mem * ak.y) * v2;                                         \
        float ppn = fmaf(ak.x, c1, pre);                                       \
        float a2n = ak.x * c2;                                                 \
        unsigned long long gg;                                                 \
        PACK2(gg, g, g);                                                       \
        unsigned long long p0, p1, p2, p3;                                     \
        MUL2(p0, CA[J].x, gg);                                                 \
        MUL2(p1, CA[J].y, gg);                                                 \
        MUL2(p2, CB[J].x, gg);                                                 \
        MUL2(p3, CB[J].y, gg);                                                 \
        FMA2(Sa01, Sa01, mm, p0);                                              \
        FMA2(Sa23, Sa23, mm, p1);                                              \
        FMA2(Sb01, Sb01, mm, p2);                                              \
        FMA2(Sb23, Sb23, mm, p3);                                              \
        greg = (lane == ((t_) & 31)) ? g : greg;                               \
        r1p = r1n; ppc = ppn; a2c = a2n;                                       \
    } while (0)

#define DRV_TILE8(CA, CB, NXA, NXB, base_, NRP)                                \
    do {                                                                       \
        DRV_STEP(CA, CB, NXA, NXB, NRP, (base_) + 0, 0);                       \
        DRV_STEP(CA, CB, NXA, NXB, NRP, (base_) + 1, 1);                       \
        DRV_STEP(CA, CB, NXA, NXB, NRP, (base_) + 2, 2);                       \
        DRV_STEP(CA, CB, NXA, NXB, NRP, (base_) + 3, 3);                       \
        DRV_STEP(CA, CB, NXA, NXB, NRP, (base_) + 4, 4);                       \
        DRV_STEP(CA, CB, NXA, NXB, NRP, (base_) + 5, 5);                       \
        DRV_STEP(CA, CB, NXA, NXB, NRP, (base_) + 6, 6);                       \
        DRV_STEP(CA, CB, NXA, NXB, NRP, (base_) + 7, 7);                       \
    } while (0)

__global__ void __launch_bounds__(32, 1)
driver_kernel(const int* __restrict__ lx,
              const float* __restrict__ effp,
              const float* __restrict__ memp,
              const float* __restrict__ boostp) {
    __shared__ float2 s_ak[TT + 4];
    __shared__ unsigned char s_lxb[TT + 4];

    int a = blockIdx.x;
    int lane = threadIdx.x;

    for (int i = lane; i < TT / 2; i += 32)
        ((float4*)s_ak)[i] = ((const float4*)g_ak)[i];
    for (int i = lane; i < TT / 4; i += 32) {
        int4 q = ((const int4*)lx)[i];
        uchar4 p;
        p.x = (unsigned char)q.x; p.y = (unsigned char)q.y;
        p.z = (unsigned char)q.z; p.w = (unsigned char)q.w;
        ((uchar4*)s_lxb)[i] = p;
    }
    __syncwarp();
    if (lane == 0) { s_ak[TT] = s_ak[TT - 1]; s_lxb[TT] = s_lxb[TT - 1]; }
    __syncwarp();

    float eff = effp[a];
    float mem = memp[a];
    float boost = boostp[a];
    float c1 = eff + boost;
    float c2 = 2.0f * boost;
    unsigned long long mm;
    PACK2(mm, mem, mem);

    unsigned long long Sa01 = 0ull, Sa23 = 0ull, Sb01 = 0ull, Sb23 = 0ull;
    float r1p = 0.5f, ppc = 0.0f, a2c = 0.0f, greg = 0.0f;
    float* gout = g_gbuf + a * GSTRIDE;

    // lane owns cols [4*lane..4*lane+3] (A) and [128+4*lane..] (B)
    const char* rb = ((const char*)g_tmg) + lane * 16;

    ulonglong2 cuA[8], cuB[8], nxA[8], nxB[8];
#pragma unroll
    for (int j = 0; j < 8; j++) {
        cuA[j] = *(const ulonglong2*)(rb + j * 1024);
        cuB[j] = *(const ulonglong2*)(rb + j * 1024 + 512);
    }

    for (int k = 0; k < 512; k += 2) {
        int k1 = (k + 1 < 511) ? (k + 1) : 511;
        int k2 = (k + 2 < 511) ? (k + 2) : 511;
        const char* n1 = rb + (size_t)k1 * 8192;
        const char* n2 = rb + (size_t)k2 * 8192;
        DRV_TILE8(cuA, cuB, nxA, nxB, k * 8, n1);
        DRV_TILE8(nxA, nxB, cuA, cuB, k * 8 + 8, n2);
        if ((k & 3) == 2) {
            gout[(k - 2) * 8 + 1 + lane] = greg;   // gS[p]=g_{p-1}
        }
    }
}

// ---------------------------------------------------------------------------
// Output: warp-per-(a,n) row, interleaved warp scan (32 consecutive positions
// per sub-chunk, one element per lane; scalar fully-coalesced LDG/STG so the
// 4097-float rows need no 16B alignment). tmS prescaled by 1/(2*diff[n]) so
// output = tanh.approx(res). Block = 8 warps = 2 algos x 4 tasks (L1 reuse).
// ---------------------------------------------------------------------------
__global__ void __launch_bounds__(256)
out_kernel(const float* __restrict__ memp,
           float* __restrict__ out) {
    int wid = threadIdx.x >> 5;
    int lane = threadIdx.x & 31;
    int bn = blockIdx.x & 63;
    int ba = blockIdx.x >> 6;
    int a = ba * 2 + (wid >> 2);
    int n = bn * 4 + (wid & 3);

    float m = memp[a];

    float mp1 = m;
    float mp2 = mp1 * mp1;
    float mp4 = mp2 * mp2;
    float mp8 = mp4 * mp4;
    float mp16 = mp8 * mp8;
    // mlane = m^lane (binary ladder)
    float mlane = 1.0f, b = m;
    if (lane & 1) mlane *= b;
    b *= b;
    if (lane & 2) mlane *= b;
    b *= b;
    if (lane & 4) mlane *= b;
    b *= b;
    if (lane & 8) mlane *= b;
    b *= b;
    if (lane & 16) mlane *= b;
    float mlp1 = mlane * m;              // m^{lane+1}

    const float* tp = g_tmS + (size_t)n * TSTRIDE;
    const float* gp = g_gbuf + (size_t)a * GSTRIDE;
    float* op = out + ((size_t)a * NT + n) * (size_t)(TT + 1);

    float carry = 0.0f;                  // scaled res at last position of prev chunk

#pragma unroll 1
    for (int it = 0; it < 32; ++it) {
        int base = it * 128 + lane;
#pragma unroll
        for (int s = 0; s < 4; ++s) {
            int q = base + s * 32;
            float c = tp[q] * gp[q];
            float x = c, v;
            v = __shfl_up_sync(0xffffffffu, x, 1);  if (lane >= 1)  x = fmaf(mp1, v, x);
            v = __shfl_up_sync(0xffffffffu, x, 2);  if (lane >= 2)  x = fmaf(mp2, v, x);
            v = __shfl_up_sync(0xffffffffu, x, 4);  if (lane >= 4)  x = fmaf(mp4, v, x);
            v = __shfl_up_sync(0xffffffffu, x, 8);  if (lane >= 8)  x = fmaf(mp8, v, x);
            v = __shfl_up_sync(0xffffffffu, x, 16); if (lane >= 16) x = fmaf(mp16, v, x);
            float res = fmaf(mlp1, carry, x);
            carry = __shfl_sync(0xffffffffu, res, 31);
            op[q] = ftanh(res);
        }
    }

    // tail element p = 4096
    if (lane == 0) {
        float c = tp[TT] * gp[TT];
        float r = fmaf(m, carry, c);
        op[TT] = ftanh(r);
    }
}

// ---------------------------------------------------------------------------
// Launch
// ---------------------------------------------------------------------------
extern "C" void kernel_launch(void* const* d_in, const int* in_sizes, int n_in,
                              void* d_out, int out_size) {
    const int* lx = (const int*)d_in[0];            // (4096,) int32
    const float* tm = (const float*)d_in[1];        // (256,256)
    const float* diff = (const float*)d_in[2];      // (256,)
    const float* eff = (const float*)d_in[3];       // (64,)
    const float* mem = (const float*)d_in[4];       // (64,)
    const float* boost = (const float*)d_in[5];     // (64,)
    float* out = (float*)d_out;                     // (64,256,4097)

    prep_kernel<<<TT, NT>>>(lx, tm, diff);
    driver_kernel<<<NA, 32>>>(lx, eff, mem, boost);
    out_kernel<<<2048, 256>>>(mem, out);
}